// round 5
// baseline (speedup 1.0000x reference)
#include <cuda_runtime.h>
#include <cstdint>

// ---------------- problem constants ----------------
#define N_SAMP 524288
#define E_NUM 16
#define HID 256
#define TILE 256                         // sorted samples per warp-tile
#define NB 128                           // blocks for hist/scatter
#define TPB_S 512
#define CHUNK (N_SAMP / NB)              // 4096
#define ITERS (CHUNK / TPB_S)            // 8
#define MAXTILES (N_SAMP / TILE + E_NUM) // 2064
#define WPB 8                            // warps per block, main kernel
#define MAIN_BLOCKS ((MAXTILES + WPB - 1) / WPB) // 258

typedef unsigned long long u64;
typedef unsigned int u32;

// ---------------- scratch (static device globals; no runtime alloc) ----------------
__device__ uint8_t g_eid[N_SAMP];
__device__ int     g_blockHist[NB * E_NUM];
__device__ int     g_cumOff[NB * E_NUM];     // exclusive block-prefix per expert
__device__ int     g_expertBase[E_NUM];
__device__ int     g_expertCnt[E_NUM];
__device__ int     g_tileBase[E_NUM + 1];
__device__ int     g_sortedIdx[N_SAMP];
__device__ float2  g_sortedXY[N_SAMP];
__device__ __align__(16) float g_dupW[E_NUM * HID * 12]; // per (e,j): {a,a,b,b, c,c,w0,w0, w1,w1,w2,w2}

// ---------------- helpers ----------------
__device__ __forceinline__ int expert_of(float x0, float x1) {
    int gi = (int)floorf(x0 * 4.0f); gi = min(max(gi, 0), 3);
    int gj = (int)floorf(x1 * 4.0f); gj = min(max(gj, 0), 3);
    return gj * 4 + gi;
}

__device__ __forceinline__ u64 pk(float lo, float hi) {
    return (u64)__float_as_uint(lo) | ((u64)__float_as_uint(hi) << 32);
}

__device__ __forceinline__ u64 ffma2(u64 a, u64 b, u64 c) {
    u64 d;
    asm("fma.rn.f32x2 %0, %1, %2, %3;" : "=l"(d) : "l"(a), "l"(b), "l"(c));
    return d;
}

__device__ __forceinline__ u64 relu2(u64 t) {
    float lo = fmaxf(__uint_as_float((u32)t), 0.0f);
    float hi = fmaxf(__uint_as_float((u32)(t >> 32)), 0.0f);
    return pk(lo, hi);
}

// ---------------- K0: build duplicated-weight table ----------------
__global__ void k0_dup(const float* __restrict__ W1, const float* __restrict__ b1,
                       const float* __restrict__ W2) {
    int t = blockIdx.x * blockDim.x + threadIdx.x; // 0..4095
    if (t >= E_NUM * HID) return;
    int e = t >> 8, j = t & 255;
    float a  = W1[e * 512 + j];         // W1[e][0][j]
    float b  = W1[e * 512 + 256 + j];   // W1[e][1][j]
    float c  = b1[e * 256 + j];
    const float* w2p = W2 + (e * 256 + j) * 3;
    float w0 = w2p[0], w1 = w2p[1], w2 = w2p[2];
    float4* dst = reinterpret_cast<float4*>(g_dupW + (size_t)t * 12);
    dst[0] = make_float4(a, a, b, b);
    dst[1] = make_float4(c, c, w0, w0);
    dst[2] = make_float4(w1, w1, w2, w2);
}

// ---------------- K1: expert ids + per-block histogram ----------------
__global__ void k1_hist(const float* __restrict__ samples) {
    __shared__ int hist[E_NUM];
    int tid = threadIdx.x, b = blockIdx.x;
    if (tid < E_NUM) hist[tid] = 0;
    __syncthreads();
    const float2* s2 = reinterpret_cast<const float2*>(samples);
#pragma unroll
    for (int k = 0; k < ITERS; k++) {
        int i = b * CHUNK + k * TPB_S + tid;
        float2 xy = s2[i];
        int e = expert_of(xy.x, xy.y);
        g_eid[i] = (uint8_t)e;
        unsigned mask = __match_any_sync(0xffffffffu, e);
        int leader = __ffs(mask) - 1;
        if ((tid & 31) == leader) atomicAdd(&hist[e], __popc(mask));
    }
    __syncthreads();
    if (tid < E_NUM) g_blockHist[b * E_NUM + tid] = hist[tid];
}

// ---------------- K2: scans (block prefix per expert, expert bases, tile table) ----------------
__global__ void k2_scan() {
    __shared__ int totals[E_NUM];
    int tid = threadIdx.x, w = tid >> 5, lane = tid & 31;
    if (w < E_NUM) {
        int run = 0;
#pragma unroll
        for (int r = 0; r < NB / 32; r++) {
            int idx = r * 32 + lane;
            int v = g_blockHist[idx * E_NUM + w];
            int s = v;
#pragma unroll
            for (int d = 1; d < 32; d <<= 1) {
                int t2 = __shfl_up_sync(0xffffffffu, s, d);
                if (lane >= d) s += t2;
            }
            g_cumOff[idx * E_NUM + w] = run + s - v; // exclusive
            run += __shfl_sync(0xffffffffu, s, 31);
        }
        if (lane == 0) totals[w] = run;
    }
    __syncthreads();
    if (tid < 32) {
        int tot = (lane < E_NUM) ? totals[lane] : 0;
        int s = tot;
#pragma unroll
        for (int d = 1; d < 32; d <<= 1) {
            int t2 = __shfl_up_sync(0xffffffffu, s, d);
            if (lane >= d) s += t2;
        }
        if (lane < E_NUM) { g_expertBase[lane] = s - tot; g_expertCnt[lane] = tot; }
        int nt = (lane < E_NUM) ? (tot + TILE - 1) / TILE : 0;
        int s2 = nt;
#pragma unroll
        for (int d = 1; d < 32; d <<= 1) {
            int t2 = __shfl_up_sync(0xffffffffu, s2, d);
            if (lane >= d) s2 += t2;
        }
        if (lane <= E_NUM) g_tileBase[lane] = s2 - nt; // lane==E_NUM: nt=0 -> total tiles
    }
}

// ---------------- K3: scatter into expert-sorted order ----------------
__global__ void k3_scatter(const float* __restrict__ samples) {
    __shared__ int sbase[E_NUM];
    __shared__ int scnt[E_NUM];
    int tid = threadIdx.x, b = blockIdx.x;
    if (tid < E_NUM) {
        sbase[tid] = g_expertBase[tid] + g_cumOff[b * E_NUM + tid];
        scnt[tid] = 0;
    }
    __syncthreads();
    const float2* s2 = reinterpret_cast<const float2*>(samples);
#pragma unroll
    for (int k = 0; k < ITERS; k++) {
        int i = b * CHUNK + k * TPB_S + tid;
        int e = g_eid[i];
        float2 xy = s2[i];
        unsigned mask = __match_any_sync(0xffffffffu, e);
        int leader = __ffs(mask) - 1;
        int base = 0;
        if ((tid & 31) == leader) base = atomicAdd(&scnt[e], __popc(mask));
        base = __shfl_sync(0xffffffffu, base, leader);
        int rank = __popc(mask & ((1u << (tid & 31)) - 1u));
        int pos = sbase[e] + base + rank;
        g_sortedIdx[pos] = i;
        g_sortedXY[pos] = xy;
    }
}

// ---------------- K4: main MoE compute (one warp per 256-sample single-expert tile) ----------------
__global__ void __launch_bounds__(WPB * 32) k4_main(const float* __restrict__ b2,
                                                    float* __restrict__ out) {
    int wid = blockIdx.x * WPB + (threadIdx.x >> 5);
    int lane = threadIdx.x & 31;
    if (wid >= g_tileBase[E_NUM]) return;

    int e = 0;
#pragma unroll
    for (int k = 1; k < E_NUM; k++)
        if (wid >= g_tileBase[k]) e = k;
    int lt = wid - g_tileBase[e];
    int start = g_expertBase[e] + lt * TILE;
    int m = min(TILE, g_expertCnt[e] - lt * TILE);

    // gather 8 samples per lane (coalesced within tile)
    int idx[8]; float2 xy[8]; bool val[8];
#pragma unroll
    for (int s = 0; s < 8; s++) {
        int o = s * 32 + lane;
        val[s] = o < m;
        int p = start + o;
        idx[s] = val[s] ? g_sortedIdx[p] : 0;
        xy[s]  = val[s] ? g_sortedXY[p] : make_float2(0.0f, 0.0f);
    }

    float bb0 = b2[e * 3], bb1 = b2[e * 3 + 1], bb2 = b2[e * 3 + 2];
    u64 B0 = pk(bb0, bb0), B1 = pk(bb1, bb1), B2 = pk(bb2, bb2);

    u64 X0[4], X1[4], Y0[4], Y1[4], Y2[4];
#pragma unroll
    for (int p = 0; p < 4; p++) {
        X0[p] = pk(xy[2 * p].x, xy[2 * p + 1].x);
        X1[p] = pk(xy[2 * p].y, xy[2 * p + 1].y);
        Y0[p] = B0; Y1[p] = B1; Y2[p] = B2;
    }

    const ulonglong2* __restrict__ wp =
        reinterpret_cast<const ulonglong2*>(g_dupW) + (size_t)e * HID * 3;

#pragma unroll 4
    for (int j = 0; j < HID; j++) {
        ulonglong2 wA = wp[j * 3];      // {aa, bb}
        ulonglong2 wB = wp[j * 3 + 1];  // {cc, w0w0}
        ulonglong2 wC = wp[j * 3 + 2];  // {w1w1, w2w2}
#pragma unroll
        for (int p = 0; p < 4; p++) {
            u64 t = ffma2(X1[p], wA.y, wB.x);   // x1*b + c
            t     = ffma2(X0[p], wA.x, t);      // x0*a + ^
            u64 h = relu2(t);
            Y0[p] = ffma2(h, wB.y, Y0[p]);
            Y1[p] = ffma2(h, wC.x, Y1[p]);
            Y2[p] = ffma2(h, wC.y, Y2[p]);
        }
    }

#pragma unroll
    for (int p = 0; p < 4; p++) {
        if (val[2 * p]) {
            float* o = out + 3 * (size_t)idx[2 * p];
            o[0] = __uint_as_float((u32)Y0[p]);
            o[1] = __uint_as_float((u32)Y1[p]);
            o[2] = __uint_as_float((u32)Y2[p]);
        }
        if (val[2 * p + 1]) {
            float* o = out + 3 * (size_t)idx[2 * p + 1];
            o[0] = __uint_as_float((u32)(Y0[p] >> 32));
            o[1] = __uint_as_float((u32)(Y1[p] >> 32));
            o[2] = __uint_as_float((u32)(Y2[p] >> 32));
        }
    }
}

// ---------------- launch ----------------
extern "C" void kernel_launch(void* const* d_in, const int* in_sizes, int n_in,
                              void* d_out, int out_size) {
    const float* samples = (const float*)d_in[0]; // [N,2]
    const float* W1      = (const float*)d_in[1]; // [16,2,256]
    const float* b1      = (const float*)d_in[2]; // [16,256]
    const float* W2      = (const float*)d_in[3]; // [16,256,3]
    const float* b2      = (const float*)d_in[4]; // [16,3]
    float* out = (float*)d_out;                   // [N,3]

    k0_dup<<<16, 256>>>(W1, b1, W2);
    k1_hist<<<NB, TPB_S>>>(samples);
    k2_scan<<<1, 512>>>();
    k3_scatter<<<NB, TPB_S>>>(samples);
    k4_main<<<MAIN_BLOCKS, WPB * 32>>>(b2, out);
}